// round 14
// baseline (speedup 1.0000x reference)
#include <cuda_runtime.h>
#include <cstdint>
#include <cstddef>

// Problem constants
#define BB   64
#define TT   1000
#define DI   128
#define RR   512
#define OO   64
#define ALPHA 0.1f            // DT/TAU

// Scan layout: 16 clusters x 8 CTAs, 4 batches/cluster (flat, no groups)
#define CSIZE 8
#define NCLUS 16
#define BPC   4               // batches per cluster
#define NTHR  512

// Scratch: precomputed input drive x_drive = input @ Wrx^T + bx  [B][T][RR]
__device__ float g_xd[(size_t)BB * TT * RR];   // 131 MB

__device__ __forceinline__ void ffma2(unsigned long long& acc,
                                      unsigned long long w,
                                      unsigned long long r) {
    asm("fma.rn.f32x2 %0,%1,%2,%0;" : "+l"(acc) : "l"(w), "l"(r));
}
__device__ __forceinline__ float unpack_sum(unsigned long long v) {
    unsigned lo, hi;
    asm("mov.b64 {%0,%1}, %2;" : "=r"(lo), "=r"(hi) : "l"(v));
    return __uint_as_float(lo) + __uint_as_float(hi);
}

// ---------------------------------------------------------------------------
// Generic small-N GEMM (x_drive precompute and output GEMM):
//   out[m][n0+n] = bias[n0+n] + sum_k A[m][k] * W[n0+n][k]
// ---------------------------------------------------------------------------
template<int K, int OUTSTRIDE>
__global__ void __launch_bounds__(256)
gemm_nt(const float* __restrict__ g_A,
        const float* __restrict__ g_W,
        const float* __restrict__ g_bias,
        float* __restrict__ g_out)
{
    __shared__ float As[64][36];
    __shared__ float Bs[32][64];

    const int tid = threadIdx.x;
    const int m0  = blockIdx.x * 64;
    const int n0  = blockIdx.y * 64;
    const int tx  = tid & 15;
    const int ty  = tid >> 4;

    unsigned long long acc[4][2];
    #pragma unroll
    for (int i = 0; i < 4; i++) { acc[i][0] = 0ull; acc[i][1] = 0ull; }

    for (int k0 = 0; k0 < K; k0 += 32) {
        #pragma unroll
        for (int q = 0; q < 2; q++) {
            int idx = tid * 2 + q;
            int m   = idx >> 3;
            int kq  = idx & 7;
            float4 v = *(const float4*)(g_A + (size_t)(m0 + m) * K + k0 + kq * 4);
            *(float4*)&As[m][kq * 4] = v;
        }
        #pragma unroll
        for (int q = 0; q < 2; q++) {
            int n  = tid >> 2;
            int kq = (tid & 3) * 2 + q;
            float4 v = *(const float4*)(g_W + (size_t)(n0 + n) * K + k0 + kq * 4);
            Bs[kq*4+0][n] = v.x;
            Bs[kq*4+1][n] = v.y;
            Bs[kq*4+2][n] = v.z;
            Bs[kq*4+3][n] = v.w;
        }
        __syncthreads();

        #pragma unroll
        for (int k = 0; k < 32; k++) {
            unsigned long long bp0 = *(const unsigned long long*)&Bs[k][tx * 4];
            unsigned long long bp1 = *(const unsigned long long*)&Bs[k][tx * 4 + 2];
            #pragma unroll
            for (int i = 0; i < 4; i++) {
                unsigned au = __float_as_uint(As[ty * 4 + i][k]);
                unsigned long long ap;
                asm("mov.b64 %0,{%1,%1};" : "=l"(ap) : "r"(au));
                ffma2(acc[i][0], ap, bp0);
                ffma2(acc[i][1], ap, bp1);
            }
        }
        __syncthreads();
    }

    float b0v = g_bias[n0 + tx * 4 + 0];
    float b1v = g_bias[n0 + tx * 4 + 1];
    float b2v = g_bias[n0 + tx * 4 + 2];
    float b3v = g_bias[n0 + tx * 4 + 3];
    #pragma unroll
    for (int i = 0; i < 4; i++) {
        unsigned u0, u1, u2, u3;
        asm("mov.b64 {%0,%1},%2;" : "=r"(u0), "=r"(u1) : "l"(acc[i][0]));
        asm("mov.b64 {%0,%1},%2;" : "=r"(u2), "=r"(u3) : "l"(acc[i][1]));
        float4 out = make_float4(__uint_as_float(u0) + b0v,
                                 __uint_as_float(u1) + b1v,
                                 __uint_as_float(u2) + b2v,
                                 __uint_as_float(u3) + b3v);
        *(float4*)(g_out + (size_t)(m0 + ty * 4 + i) * OUTSTRIDE + n0 + tx * 4) = out;
    }
}

// ---------------------------------------------------------------------------
// Flat single-barrier persistent scan (R11 schedule, 4 batches, 16 clusters).
// Per step: fused GEMM(4 batches) -> sync -> reduce(256 thr)+stage snew ->
// arrive -> [STG rstore + prefetch t+1 hidden in barrier window] -> wait ->
// ONE remote float4 pull per thread -> land -> sync.
// Thread = (2 neurons, 32-k slice); Wrr slice in registers.
// ---------------------------------------------------------------------------
__global__ void __cluster_dims__(CSIZE, 1, 1) __launch_bounds__(NTHR, 1)
ctrnn_scan(const float* __restrict__ g_br,   // [B][T][RR]
           const float* __restrict__ g_Wrr,  // [RR][RR]
           const float* __restrict__ g_r0,   // [RR]
           float* __restrict__ g_rstore)     // [B][T][RR]
{
    __shared__ __align__(16) float rbuf[BPC][RR];      //  8 KB
    __shared__ __align__(16) float pz[16][BPC][64];    // 16 KB
    __shared__ __align__(16) float snew[2][BPC][64];   //  2 KB [par][b][j]

    const int w   = blockIdx.x;      // cluster rank 0..7
    const int c   = blockIdx.y;      // cluster id 0..15
    const int tid = threadIdx.x;
    const int jp  = tid & 31;        // neuron-pair index
    const int kg  = tid >> 5;        // k-group 0..15 (32 k each)
    const int j0  = jp * 2;
    const int jg0 = w * 64 + j0;
    const int b0  = c * BPC;

    // ---- one-time: Wrr slice (2 neurons x 32 k) as packed f32x2 pairs ----
    unsigned long long wrrp[2][16];
    #pragma unroll
    for (int jj = 0; jj < 2; jj++) {
        const ulonglong2* src =
            (const ulonglong2*)(g_Wrr + (size_t)(jg0 + jj) * RR + kg * 32);
        #pragma unroll
        for (int q = 0; q < 8; q++) {
            ulonglong2 v = src[q];
            wrrp[jj][2*q+0] = v.x;
            wrrp[jj][2*q+1] = v.y;
        }
    }

    // reducer indices (tid<256)
    const int rb = tid >> 6;          // batch 0..3
    const int rj = tid & 63;          // neuron
    const int colj = w * 64 + rj;
    const size_t row = ((size_t)(b0 + rb)) * TT;
    // pull indices (all 512 threads): exactly one float4 each
    const int pb    = tid >> 7;       // batch 0..3
    const int pk4   = tid & 127;      // float4 index into 512 neurons
    const int prank = pk4 >> 4;       // owning CTA rank
    const int pj4   = pk4 & 15;

    // ---- init rbuf from r0; prefetch t=0 ----
    {
        float v = g_r0[tid];
        #pragma unroll
        for (int b = 0; b < BPC; b++) rbuf[b][tid] = v;
    }
    float brv = 0.f, xdv = 0.f;
    if (tid < 256) {
        brv = g_br[(row + 0) * RR + colj];
        xdv = g_xd[(row + 0) * RR + colj];
    }
    __syncthreads();

    const ulonglong2* ru = (const ulonglong2*)rbuf;   // [b*128 + k4]

    for (int t = 0; t < TT; t++) {
        const int par = t & 1;

        // ================= fused GEMM: 2n x 32k x 4b per thread =============
        {
            unsigned long long acc0[4] = {0ull,0ull,0ull,0ull};
            unsigned long long acc1[4] = {0ull,0ull,0ull,0ull};
            const int kb = kg * 8;
            #pragma unroll
            for (int ch = 0; ch < 8; ch++) {
                #pragma unroll
                for (int b = 0; b < 4; b++) {
                    ulonglong2 rv = ru[b * 128 + kb + ch];
                    ffma2(acc0[b], wrrp[0][2*ch+0], rv.x);
                    ffma2(acc0[b], wrrp[0][2*ch+1], rv.y);
                    ffma2(acc1[b], wrrp[1][2*ch+0], rv.x);
                    ffma2(acc1[b], wrrp[1][2*ch+1], rv.y);
                }
            }
            #pragma unroll
            for (int b = 0; b < 4; b++)
                *(float2*)&pz[kg][b][j0] =
                    make_float2(unpack_sum(acc0[b]), unpack_sum(acc1[b]));
        }
        __syncthreads();   // pz complete

        // ---- reduce 16 k-groups, fast retanh, leaky update, stage ----
        float rn = 0.f;
        if (tid < 256) {
            float s0 = 0.f, s1 = 0.f;
            #pragma unroll
            for (int g = 0; g < 16; g += 2) {
                s0 += pz[g][rb][rj];
                s1 += pz[g+1][rb][rj];
            }
            float z = xdv + s0 + s1;
            float e = __expf(2.0f * z);
            float f = (z > 0.f) ? (1.0f - __fdividef(2.0f, e + 1.0f)) : 0.0f;
            float rold = rbuf[rb][colj];
            rn = fmaf(ALPHA, f + brv - rold, rold);
            snew[par][rb][rj] = rn;
        }

        // ---- single barrier round; STG + prefetch hidden in the window ----
        asm volatile("barrier.cluster.arrive.aligned;" ::: "memory");
        if (tid < 256) {
            g_rstore[(row + t) * RR + colj] = rn;
            if (t + 1 < TT) {
                brv = g_br[(row + t + 1) * RR + colj];
                xdv = g_xd[(row + t + 1) * RR + colj];
            }
        }
        asm volatile("barrier.cluster.wait.aligned;" ::: "memory");

        // ---- pull: exactly one remote float4 per thread, land in rbuf ----
        {
            unsigned l = (unsigned)__cvta_generic_to_shared(
                             &snew[par][pb][pj4 * 4]);
            unsigned r;
            asm("mapa.shared::cluster.u32 %0, %1, %2;"
                : "=r"(r) : "r"(l), "r"(prank));
            float x, y2, z2, w2;
            asm volatile("ld.shared::cluster.v4.f32 {%0,%1,%2,%3},[%4];"
                         : "=f"(x), "=f"(y2), "=f"(z2), "=f"(w2) : "r"(r));
            *(float4*)&rbuf[pb][pk4 * 4] = make_float4(x, y2, z2, w2);
        }
        __syncthreads();   // rbuf(t+1) ready
    }

    // keep SMEM alive until all peers' final remote reads complete
    asm volatile("barrier.cluster.arrive.aligned;" ::: "memory");
    asm volatile("barrier.cluster.wait.aligned;"   ::: "memory");
}

__global__ void ctrnn_nop() {}

// ---------------------------------------------------------------------------
// Output layout: [ y (B*T*OO) | rstore (B*T*RR) ]
// ---------------------------------------------------------------------------
extern "C" void kernel_launch(void* const* d_in, const int* in_sizes, int n_in,
                              void* d_out, int out_size)
{
    const float* input = (const float*)d_in[0];
    const float* br    = (const float*)d_in[1];
    const float* Wrx   = (const float*)d_in[2];
    const float* bx    = (const float*)d_in[3];
    const float* Wrr   = (const float*)d_in[4];
    const float* Wyr   = (const float*)d_in[5];
    const float* by    = (const float*)d_in[6];
    const float* r0    = (const float*)d_in[7];

    float* y      = (float*)d_out;
    float* rstore = (float*)d_out + (size_t)BB * TT * OO;

    float* xd = nullptr;
    cudaGetSymbolAddress((void**)&xd, g_xd);

    // 1) x_drive = input @ Wrx^T + bx   [64000 x 512], K=128
    {
        dim3 g((BB * TT) / 64, RR / 64);
        gemm_nt<DI, RR><<<g, 256>>>(input, Wrx, bx, xd);
    }
    // 2) recurrence (flat single-barrier, 4 batches x 16 clusters)
    {
        dim3 grid(CSIZE, NCLUS, 1);
        ctrnn_scan<<<grid, NTHR>>>(br, Wrr, r0, rstore);
    }
    // 3) y = rstore @ Wyr^T + by        [64000 x 64], K=512
    {
        dim3 g((BB * TT) / 64, OO / 64);
        gemm_nt<RR, OO><<<g, 256>>>(rstore, Wyr, by, y);
    }
    ctrnn_nop<<<1, 32>>>();
    ctrnn_nop<<<1, 32>>>();
}

// round 15
// speedup vs baseline: 1.2634x; 1.2634x over previous
#include <cuda_runtime.h>
#include <cstdint>
#include <cstddef>

// Problem constants
#define BB   64
#define TT   1000
#define DI   128
#define RR   512
#define OO   64
#define ALPHA 0.1f            // DT/TAU

// Scan layout: 8 clusters x 8 CTAs, 8 batches/cluster (2 groups of 4)
#define CSIZE 8
#define NCLUS 8
#define BPG   4               // batches per group
#define NTHR  512

// Scratch: precomputed input drive x_drive = input @ Wrx^T + bx  [B][T][RR]
__device__ float g_xd[(size_t)BB * TT * RR];   // 131 MB

__device__ __forceinline__ void ffma2(unsigned long long& acc,
                                      unsigned long long w,
                                      unsigned long long r) {
    asm("fma.rn.f32x2 %0,%1,%2,%0;" : "+l"(acc) : "l"(w), "l"(r));
}
__device__ __forceinline__ float unpack_sum(unsigned long long v) {
    unsigned lo, hi;
    asm("mov.b64 {%0,%1}, %2;" : "=r"(lo), "=r"(hi) : "l"(v));
    return __uint_as_float(lo) + __uint_as_float(hi);
}

// ---------------------------------------------------------------------------
// Generic small-N GEMM (x_drive precompute and output GEMM):
//   out[m][n0+n] = bias[n0+n] + sum_k A[m][k] * W[n0+n][k]
// ---------------------------------------------------------------------------
template<int K, int OUTSTRIDE>
__global__ void __launch_bounds__(256)
gemm_nt(const float* __restrict__ g_A,
        const float* __restrict__ g_W,
        const float* __restrict__ g_bias,
        float* __restrict__ g_out)
{
    __shared__ float As[64][36];
    __shared__ float Bs[32][64];

    const int tid = threadIdx.x;
    const int m0  = blockIdx.x * 64;
    const int n0  = blockIdx.y * 64;
    const int tx  = tid & 15;
    const int ty  = tid >> 4;

    unsigned long long acc[4][2];
    #pragma unroll
    for (int i = 0; i < 4; i++) { acc[i][0] = 0ull; acc[i][1] = 0ull; }

    for (int k0 = 0; k0 < K; k0 += 32) {
        #pragma unroll
        for (int q = 0; q < 2; q++) {
            int idx = tid * 2 + q;
            int m   = idx >> 3;
            int kq  = idx & 7;
            float4 v = *(const float4*)(g_A + (size_t)(m0 + m) * K + k0 + kq * 4);
            *(float4*)&As[m][kq * 4] = v;
        }
        #pragma unroll
        for (int q = 0; q < 2; q++) {
            int n  = tid >> 2;
            int kq = (tid & 3) * 2 + q;
            float4 v = *(const float4*)(g_W + (size_t)(n0 + n) * K + k0 + kq * 4);
            Bs[kq*4+0][n] = v.x;
            Bs[kq*4+1][n] = v.y;
            Bs[kq*4+2][n] = v.z;
            Bs[kq*4+3][n] = v.w;
        }
        __syncthreads();

        #pragma unroll
        for (int k = 0; k < 32; k++) {
            unsigned long long bp0 = *(const unsigned long long*)&Bs[k][tx * 4];
            unsigned long long bp1 = *(const unsigned long long*)&Bs[k][tx * 4 + 2];
            #pragma unroll
            for (int i = 0; i < 4; i++) {
                unsigned au = __float_as_uint(As[ty * 4 + i][k]);
                unsigned long long ap;
                asm("mov.b64 %0,{%1,%1};" : "=l"(ap) : "r"(au));
                ffma2(acc[i][0], ap, bp0);
                ffma2(acc[i][1], ap, bp1);
            }
        }
        __syncthreads();
    }

    float b0v = g_bias[n0 + tx * 4 + 0];
    float b1v = g_bias[n0 + tx * 4 + 1];
    float b2v = g_bias[n0 + tx * 4 + 2];
    float b3v = g_bias[n0 + tx * 4 + 3];
    #pragma unroll
    for (int i = 0; i < 4; i++) {
        unsigned u0, u1, u2, u3;
        asm("mov.b64 {%0,%1},%2;" : "=r"(u0), "=r"(u1) : "l"(acc[i][0]));
        asm("mov.b64 {%0,%1},%2;" : "=r"(u2), "=r"(u3) : "l"(acc[i][1]));
        float4 out = make_float4(__uint_as_float(u0) + b0v,
                                 __uint_as_float(u1) + b1v,
                                 __uint_as_float(u2) + b2v,
                                 __uint_as_float(u3) + b3v);
        *(float4*)(g_out + (size_t)(m0 + ty * 4 + i) * OUTSTRIDE + n0 + tx * 4) = out;
    }
}

// ---------------------------------------------------------------------------
// Minimal single-barrier split-group persistent scan (R11 simplified).
// Cluster = 8 batches: group A (b0..b0+3), group B (b0+4..b0+7).
// Per step: GEMM_A; GEMM_B (no sync between: disjoint pz, read-only rbufs);
// sync; combined reduce (512 thr, both groups) + stage snew[par]; arrive;
// STG rstore + prefetch t+1 (hidden in barrier window); wait;
// pullA+pullB (MLP=2); land both; sync.
// Thread = (2 neurons, 32-k slice); Wrr slice in registers.
// ---------------------------------------------------------------------------
struct ScanSmem {
    float rbuf[2][BPG][RR];        // 16 KB  [grp][b][k]
    float pz[2][16][BPG][64];      // 32 KB  [grp][kg][b][j]
    float snew[2][2][BPG][64];     //  4 KB  [par][grp][b][j]
};
#define SCAN_SMEM_BYTES ((int)sizeof(ScanSmem))

__global__ void __cluster_dims__(CSIZE, 1, 1) __launch_bounds__(NTHR, 1)
ctrnn_scan(const float* __restrict__ g_br,   // [B][T][RR]
           const float* __restrict__ g_Wrr,  // [RR][RR]
           const float* __restrict__ g_r0,   // [RR]
           float* __restrict__ g_rstore)     // [B][T][RR]
{
    extern __shared__ __align__(16) char smem_raw[];
    ScanSmem* s = (ScanSmem*)smem_raw;

    const int w   = blockIdx.x;      // cluster rank 0..7
    const int c   = blockIdx.y;      // cluster id 0..7
    const int tid = threadIdx.x;
    const int jp  = tid & 31;        // neuron-pair index
    const int kg  = tid >> 5;        // k-group 0..15 (32 k each)
    const int j0  = jp * 2;
    const int jg0 = w * 64 + j0;
    const int b0  = c * (2 * BPG);   // first batch of this cluster

    // ---- one-time: Wrr slice (2 neurons x 32 k) as packed f32x2 pairs ----
    unsigned long long wrrp[2][16];
    #pragma unroll
    for (int jj = 0; jj < 2; jj++) {
        const ulonglong2* src =
            (const ulonglong2*)(g_Wrr + (size_t)(jg0 + jj) * RR + kg * 32);
        #pragma unroll
        for (int q = 0; q < 8; q++) {
            ulonglong2 v = src[q];
            wrrp[jj][2*q+0] = v.x;
            wrrp[jj][2*q+1] = v.y;
        }
    }

    // combined-reduce role (all 512 threads): group, batch-in-group, neuron
    const int rg   = tid >> 8;        // 0..1
    const int ridx = tid & 255;
    const int rb   = ridx >> 6;       // 0..3
    const int rj   = ridx & 63;
    const int colj = w * 64 + rj;
    const size_t row = ((size_t)(b0 + rg * BPG + rb)) * TT;

    // pull role (all 512 threads): one float4 per group
    const int pb    = tid >> 7;       // batch-in-group 0..3
    const int pk4   = tid & 127;      // float4 index into 512 neurons
    const int prank = pk4 >> 4;       // owning CTA rank
    const int pj4   = pk4 & 15;

    // ---- init both r buffers from r0 ----
    {
        float v = g_r0[tid];
        #pragma unroll
        for (int b = 0; b < BPG; b++) {
            s->rbuf[0][b][tid] = v;
            s->rbuf[1][b][tid] = v;
        }
    }
    // prologue prefetch (t=0)
    float brv = g_br[(row + 0) * RR + colj];
    float xdv = g_xd[(row + 0) * RR + colj];
    __syncthreads();

    const ulonglong2* ruA = (const ulonglong2*)s->rbuf[0];
    const ulonglong2* ruB = (const ulonglong2*)s->rbuf[1];

    for (int t = 0; t < TT; t++) {
        const int par = t & 1;

        // ================= GEMM A -> pz[0] =================
        {
            unsigned long long acc0[4] = {0ull,0ull,0ull,0ull};
            unsigned long long acc1[4] = {0ull,0ull,0ull,0ull};
            const int kb = kg * 8;
            #pragma unroll
            for (int ch = 0; ch < 8; ch++) {
                #pragma unroll
                for (int b = 0; b < 4; b++) {
                    ulonglong2 rv = ruA[b * 128 + kb + ch];
                    ffma2(acc0[b], wrrp[0][2*ch+0], rv.x);
                    ffma2(acc0[b], wrrp[0][2*ch+1], rv.y);
                    ffma2(acc1[b], wrrp[1][2*ch+0], rv.x);
                    ffma2(acc1[b], wrrp[1][2*ch+1], rv.y);
                }
            }
            #pragma unroll
            for (int b = 0; b < 4; b++)
                *(float2*)&s->pz[0][kg][b][j0] =
                    make_float2(unpack_sum(acc0[b]), unpack_sum(acc1[b]));
        }

        // ================= GEMM B -> pz[1] (no sync needed between) ========
        {
            unsigned long long acc0[4] = {0ull,0ull,0ull,0ull};
            unsigned long long acc1[4] = {0ull,0ull,0ull,0ull};
            const int kb = kg * 8;
            #pragma unroll
            for (int ch = 0; ch < 8; ch++) {
                #pragma unroll
                for (int b = 0; b < 4; b++) {
                    ulonglong2 rv = ruB[b * 128 + kb + ch];
                    ffma2(acc0[b], wrrp[0][2*ch+0], rv.x);
                    ffma2(acc0[b], wrrp[0][2*ch+1], rv.y);
                    ffma2(acc1[b], wrrp[1][2*ch+0], rv.x);
                    ffma2(acc1[b], wrrp[1][2*ch+1], rv.y);
                }
            }
            #pragma unroll
            for (int b = 0; b < 4; b++)
                *(float2*)&s->pz[1][kg][b][j0] =
                    make_float2(unpack_sum(acc0[b]), unpack_sum(acc1[b]));
        }
        __syncthreads();   // sync 1: all pz complete

        // ---- combined reduce (all 512 threads), retanh, update, stage ----
        float rn;
        {
            float s0 = 0.f, s1 = 0.f;
            #pragma unroll
            for (int gg = 0; gg < 16; gg += 2) {
                s0 += s->pz[rg][gg][rb][rj];
                s1 += s->pz[rg][gg+1][rb][rj];
            }
            float z = xdv + s0 + s1;
            float e = __expf(2.0f * z);
            float f = (z > 0.f) ? (1.0f - __fdividef(2.0f, e + 1.0f)) : 0.0f;
            float rold = s->rbuf[rg][rb][colj];
            rn = fmaf(ALPHA, f + brv - rold, rold);
            s->snew[par][rg][rb][rj] = rn;
        }

        // ---- single barrier round; STG + prefetch hidden in the window ----
        asm volatile("barrier.cluster.arrive.aligned;" ::: "memory");
        g_rstore[(row + t) * RR + colj] = rn;
        if (t + 1 < TT) {
            brv = g_br[(row + t + 1) * RR + colj];
            xdv = g_xd[(row + t + 1) * RR + colj];
        }
        asm volatile("barrier.cluster.wait.aligned;" ::: "memory");

        // ---- pulls: both issued together (MLP=2), land both ----
        {
            unsigned lA = (unsigned)__cvta_generic_to_shared(
                              &s->snew[par][0][pb][pj4 * 4]);
            unsigned lB = (unsigned)__cvta_generic_to_shared(
                              &s->snew[par][1][pb][pj4 * 4]);
            unsigned rA, rB;
            asm("mapa.shared::cluster.u32 %0, %1, %2;" : "=r"(rA) : "r"(lA), "r"(prank));
            asm("mapa.shared::cluster.u32 %0, %1, %2;" : "=r"(rB) : "r"(lB), "r"(prank));
            float ax, ay, az, aw, bx2, by2, bz2, bw2;
            asm volatile("ld.shared::cluster.v4.f32 {%0,%1,%2,%3},[%4];"
                         : "=f"(ax), "=f"(ay), "=f"(az), "=f"(aw) : "r"(rA));
            asm volatile("ld.shared::cluster.v4.f32 {%0,%1,%2,%3},[%4];"
                         : "=f"(bx2), "=f"(by2), "=f"(bz2), "=f"(bw2) : "r"(rB));
            *(float4*)&s->rbuf[0][pb][pk4 * 4] = make_float4(ax, ay, az, aw);
            *(float4*)&s->rbuf[1][pb][pk4 * 4] = make_float4(bx2, by2, bz2, bw2);
        }
        __syncthreads();   // sync 2: rbufs ready for next step
    }

    // keep SMEM alive until all peers' final remote reads complete
    asm volatile("barrier.cluster.arrive.aligned;" ::: "memory");
    asm volatile("barrier.cluster.wait.aligned;"   ::: "memory");
}

__global__ void ctrnn_nop() {}

// ---------------------------------------------------------------------------
// Output layout: [ y (B*T*OO) | rstore (B*T*RR) ]
// ---------------------------------------------------------------------------
extern "C" void kernel_launch(void* const* d_in, const int* in_sizes, int n_in,
                              void* d_out, int out_size)
{
    const float* input = (const float*)d_in[0];
    const float* br    = (const float*)d_in[1];
    const float* Wrx   = (const float*)d_in[2];
    const float* bx    = (const float*)d_in[3];
    const float* Wrr   = (const float*)d_in[4];
    const float* Wyr   = (const float*)d_in[5];
    const float* by    = (const float*)d_in[6];
    const float* r0    = (const float*)d_in[7];

    float* y      = (float*)d_out;
    float* rstore = (float*)d_out + (size_t)BB * TT * OO;

    float* xd = nullptr;
    cudaGetSymbolAddress((void**)&xd, g_xd);

    static bool attr_done = false;
    if (!attr_done) {
        cudaFuncSetAttribute(ctrnn_scan,
                             cudaFuncAttributeMaxDynamicSharedMemorySize,
                             SCAN_SMEM_BYTES);
        attr_done = true;
    }

    // 1) x_drive = input @ Wrx^T + bx   [64000 x 512], K=128
    {
        dim3 g((BB * TT) / 64, RR / 64);
        gemm_nt<DI, RR><<<g, 256>>>(input, Wrx, bx, xd);
    }
    // 2) recurrence (minimal single-barrier, 8 batches x 8 clusters)
    {
        dim3 grid(CSIZE, NCLUS, 1);
        ctrnn_scan<<<grid, NTHR, SCAN_SMEM_BYTES>>>(br, Wrr, r0, rstore);
    }
    // 3) y = rstore @ Wyr^T + by        [64000 x 64], K=512
    {
        dim3 g((BB * TT) / 64, OO / 64);
        gemm_nt<RR, OO><<<g, 256>>>(rstore, Wyr, by, y);
    }
    ctrnn_nop<<<1, 32>>>();
    ctrnn_nop<<<1, 32>>>();
}